// round 14
// baseline (speedup 1.0000x reference)
#include <cuda_runtime.h>
#include <cuda_fp16.h>
#include <cstdint>

#define NB   16
#define SEQ  1024
#define HID  768
#define SCALE_QK 0.03608439182435161f

#define BM 128
#define BN 128
#define BK 32
#define NTHREADS 128
#define STG 10240            /* one operand tile: 128 rows * 80B */
#define STAGE_BYTES 20480    /* A + B */
#define NSTAGES 4
#define SMEM_GEMM (NSTAGES*STAGE_BYTES)   /* 80 KB -> 2 CTAs/SM */

typedef __half fp16;

/* ------------------ scratch (device globals, zero-initialized) ------------ */
#define NXE 12582912   /* 16*1024*768 */
#define NWE 589824     /* 768*768 */
#define NSE 16777216   /* 16*1024*1024 */
__device__ fp16 g_xc[NXE];                 /* compacted x rows (fp16) */
__device__ fp16 g_q [NXE];                 /* compact q */
__device__ fp16 g_k [NXE];                 /* compact k */
__device__ fp16 g_v [NXE];                 /* compact v */
__device__ fp16 g_oc[NXE];                 /* compact attention out */
__device__ fp16 g_h1[NXE];                 /* compact ffn hidden */
__device__ fp16 g_wqkv[3*NWE];
__device__ fp16 g_w1[NWE], g_w2[NWE];
__device__ float g_sc[NSE];                /* compact scores, ld=1024 */
__device__ fp16 g_w [NSE];                 /* compact softmax weights, K zero-padded */
__device__ int  g_idx[NB*SEQ];
__device__ int  g_cnt[NB];
__device__ float g_cvec[HID];              /* constant out row for masked rows */

/* ------------------ helpers ------------------ */
static __device__ __forceinline__ uint32_t smem_u32(const void* p) {
    uint32_t a;
    asm("{ .reg .u64 t; cvta.to.shared.u64 t, %1; cvt.u32.u64 %0, t; }" : "=r"(a) : "l"(p));
    return a;
}
static __device__ __forceinline__ uint32_t pack_h2(float v0, float v1) {
    __half2 h = __floats2half2_rn(v0, v1);
    return *reinterpret_cast<uint32_t*>(&h);
}

#define CP16(dst, src) \
    asm volatile("cp.async.cg.shared.global [%0], [%1], 16;" :: "r"(dst), "l"(src))
#define CPCOMMIT() asm volatile("cp.async.commit_group;" ::: "memory")
#define CPWAIT2()  asm volatile("cp.async.wait_group 2;" ::: "memory")

#define LDSM4(r, a) \
    asm volatile("ldmatrix.sync.aligned.m8n8.x4.shared.b16 {%0,%1,%2,%3}, [%4];" \
        : "=r"((r)[0]),"=r"((r)[1]),"=r"((r)[2]),"=r"((r)[3]) : "r"(a))
#define LDSM4T(r, a) \
    asm volatile("ldmatrix.sync.aligned.m8n8.x4.trans.shared.b16 {%0,%1,%2,%3}, [%4];" \
        : "=r"((r)[0]),"=r"((r)[1]),"=r"((r)[2]),"=r"((r)[3]) : "r"(a))
#define MMA(c, a, b0, b1) \
    asm volatile("mma.sync.aligned.m16n8k16.row.col.f32.f16.f16.f32 " \
        "{%0,%1,%2,%3}, {%4,%5,%6,%7}, {%8,%9}, {%0,%1,%2,%3};" \
        : "+f"((c)[0]), "+f"((c)[1]), "+f"((c)[2]), "+f"((c)[3]) \
        : "r"((a)[0]),"r"((a)[1]),"r"((a)[2]),"r"((a)[3]), "r"(b0), "r"(b1))

/* ---- per-batch compaction index (1 warp per batch, ballot scan) ---- */
__global__ __launch_bounds__(32) void idx_kernel(
    const int* __restrict__ mask, int* __restrict__ gidx, int* __restrict__ cnt)
{
    const int b = blockIdx.x, lane = threadIdx.x;
    int c = 0;
    for (int s0 = 0; s0 < SEQ; s0 += 32) {
        const int v = mask[b * SEQ + s0 + lane];
        const unsigned bal = __ballot_sync(~0u, v != 0);
        const int pos = c + __popc(bal & ((1u << lane) - 1u));
        if (v) gidx[b * SEQ + pos] = s0 + lane;
        c += __popc(bal);
    }
    if (lane == 0) cnt[b] = c;
}

/* ---- gather + fp32->fp16 convert compacted x rows ---- */
__global__ __launch_bounds__(192) void gather_x_kernel(
    const float* __restrict__ x, const int* __restrict__ gidx,
    const int* __restrict__ cnt, uint32_t* __restrict__ xc)
{
    const int j = blockIdx.x, b = blockIdx.y, t = threadIdx.x;
    if (j >= cnt[b]) return;
    const int s = gidx[b * SEQ + j];
    const float4 v = reinterpret_cast<const float4*>(x + ((size_t)b * SEQ + s) * HID)[t];
    uint2 o;
    o.x = pack_h2(v.x, v.y);
    o.y = pack_h2(v.z, v.w);
    reinterpret_cast<uint2*>(xc + ((size_t)b * SEQ + j) * (HID / 2))[t] = o;
}

/* ---- weight converts ---- */
__global__ __launch_bounds__(256) void cvt_w3_kernel(
    const float* __restrict__ s0, const float* __restrict__ s1,
    const float* __restrict__ s2, uint32_t* __restrict__ wqkv, int n2)
{
    int i = blockIdx.x * 256 + threadIdx.x;
    if (i >= n2) return;
    const int y = blockIdx.y;
    const float* s = (y == 0) ? s0 : (y == 1) ? s1 : s2;
    float2 v = reinterpret_cast<const float2*>(s)[i];
    wqkv[(size_t)y * n2 + i] = pack_h2(v.x, v.y);
}
__global__ __launch_bounds__(256) void cvt_w2_kernel(
    const float* __restrict__ s0, const float* __restrict__ s1,
    uint32_t* __restrict__ w1, uint32_t* __restrict__ w2, int n2)
{
    int i = blockIdx.x * 256 + threadIdx.x;
    if (i >= n2) return;
    const float* s = blockIdx.y ? s1 : s0;
    uint32_t* d = blockIdx.y ? w2 : w1;
    float2 v = reinterpret_cast<const float2*>(s)[i];
    d[i] = pack_h2(v.x, v.y);
}

/* ---- constant masked-row output: cvec = relu(b1) @ W2^T + b2 (exact fp32) ---- */
__global__ __launch_bounds__(128) void cvec_kernel(
    const float* __restrict__ b1, const float* __restrict__ W2,
    const float* __restrict__ b2, float* __restrict__ cvec)
{
    const int o = blockIdx.x * 128 + threadIdx.x;
    float s = b2[o];
    for (int h = 0; h < HID; h++)
        s = fmaf(fmaxf(b1[h], 0.f), W2[(size_t)o * HID + h], s);
    cvec[o] = s;
}

/* ---- fill masked rows of the dense output with cvec ---- */
__global__ __launch_bounds__(192) void fill_masked_kernel(
    const int* __restrict__ mask, const float* __restrict__ cvec,
    float* __restrict__ out)
{
    const int s = blockIdx.x, b = blockIdx.y, t = threadIdx.x;
    if (mask[b * SEQ + s]) return;
    const float4 v = reinterpret_cast<const float4*>(cvec)[t];
    reinterpret_cast<float4*>(out + ((size_t)b * SEQ + s) * HID)[t] = v;
}

/* ---------------------------------------------------------------------------
 * fp16 GEMM, mma.sync m16n8k16, fp32 acc. CTA 128x128xBK32, warp tile 64x64,
 * 4-stage cp.async, 2 CTAs/SM. All compact-M (guarded by cnt[z]).
 * NN=0: C=A*B^T (K-major); NN=1: C=A*B (B N-major, ldbn row stride).
 * MODE 1: scores: M,N guarded; fp32 out (ld 1024), *SCALE.
 * MODE 2: fused qkv: N spans 3 HID segments -> q/k/v, relu on segs 0,1.
 * MODE 3: compact generic: bias/relu opt, resh compact fp16 residual opt,
 *         Ch compact fp16 out opt, Cf = DENSE fp32 out scattered via gidx opt.
 *         If NN==1, K = pad32(cnt[z]) (PV case).
 * ------------------------------------------------------------------------ */
template<int NN, int MODE>
__global__ __launch_bounds__(NTHREADS, 2) void gemm_fp16(
    const fp16* __restrict__ A, const fp16* __restrict__ B,
    int K, int lda, int ldbn,
    size_t sA, size_t sB, size_t sC,
    float* __restrict__ Cf, fp16* __restrict__ Ch,
    fp16* __restrict__ Ch2, fp16* __restrict__ Ch3,
    int ldc,
    const float* __restrict__ bias, const float* __restrict__ bias2,
    const float* __restrict__ bias3,
    const fp16* __restrict__ resh,
    const int* __restrict__ cnt, const int* __restrict__ gidx, int relu)
{
    extern __shared__ char smraw[];
    const uint32_t sb = smem_u32(smraw);
    const int tid = threadIdx.x, lane = tid & 31, wid = tid >> 5;
    const int wm = wid & 1, wn = wid >> 1;
    const int z = blockIdx.z, bm = blockIdx.y * BM, bn = blockIdx.x * BN;

    const int nb = __ldg(cnt + z);
    if (bm >= nb) return;
    if (MODE == 1 && bn >= nb) return;
    if (MODE == 3 && NN == 1) K = (nb + 31) & ~31;

    const fp16* Ag = A + z * sA + (size_t)bm * lda;
    const fp16* Bg;
    if (NN) Bg = B + z * sB + bn;
    else    Bg = B + z * sB + (size_t)bn * K;

    float acc[4][8][4];
    #pragma unroll
    for (int i = 0; i < 4; i++)
        #pragma unroll
        for (int j = 0; j < 8; j++)
            #pragma unroll
            for (int t = 0; t < 4; t++) acc[i][j][t] = 0.f;

    auto issue = [&](int s) {
        const uint32_t stb = sb + (uint32_t)(s % NSTAGES) * STAGE_BYTES;
        const int k0 = s * BK;
        #pragma unroll
        for (int i = 0; i < 4; i++) {
            const int idx = tid + (i << 7);
            const int row = idx >> 2, c8 = (idx & 3) << 3;
            CP16(stb + row * 80 + (c8 << 1), Ag + (size_t)row * lda + k0 + c8);
        }
        if (!NN) {
            #pragma unroll
            for (int i = 0; i < 4; i++) {
                const int idx = tid + (i << 7);
                const int row = idx >> 2, c8 = (idx & 3) << 3;
                CP16(stb + STG + row * 80 + (c8 << 1), Bg + (size_t)row * K + k0 + c8);
            }
        } else {
            #pragma unroll
            for (int i = 0; i < 4; i++) {
                const int idx = tid + (i << 7);
                const int row = idx >> 4, c8 = (idx & 15) << 3;
                CP16(stb + STG + row * 272 + (c8 << 1), Bg + (size_t)(k0 + row) * ldbn + c8);
            }
        }
    };

    auto compute = [&](int s) {
        const uint32_t stb = sb + (uint32_t)(s % NSTAGES) * STAGE_BYTES;
        #pragma unroll
        for (int ks = 0; ks < 2; ks++) {
            uint32_t ah[4][4];
            #pragma unroll
            for (int i = 0; i < 4; i++) {
                const int arow = wm * 64 + i * 16 + (lane & 15);
                LDSM4(ah[i], stb + arow * 80 + ((ks * 16 + ((lane >> 4) << 3)) << 1));
            }
            #pragma unroll
            for (int p = 0; p < 4; p++) {
                uint32_t bh[4];
                if (!NN) {
                    const int brow = wn * 64 + p * 16 + (lane & 7) + ((lane >> 4) << 3);
                    LDSM4(bh, stb + STG + brow * 80 +
                              ((ks * 16 + (((lane >> 3) & 1) << 3)) << 1));
                } else {
                    const int krow = ks * 16 + (lane & 7) + (((lane >> 3) & 1) << 3);
                    const int ncol = wn * 64 + p * 16 + ((lane >> 4) << 3);
                    LDSM4T(bh, stb + STG + krow * 272 + (ncol << 1));
                }
                #pragma unroll
                for (int i = 0; i < 4; i++)
                    #pragma unroll
                    for (int jj = 0; jj < 2; jj++)
                        MMA(acc[i][p * 2 + jj], ah[i], bh[jj * 2], bh[jj * 2 + 1]);
            }
        }
    };

    const int NSt = K / BK;
    issue(0); CPCOMMIT();
    if (NSt > 1) issue(1); CPCOMMIT();
    if (NSt > 2) issue(2); CPCOMMIT();
    for (int s = 0; s < NSt; s++) {
        CPWAIT2();
        __syncthreads();
        if (s + 3 < NSt) issue(s + 3);
        CPCOMMIT();
        compute(s);
    }

    /* ---- epilogue ---- */
    if (MODE == 1) {                       /* compact scores, fp32 */
        float* Cfz = Cf + (size_t)z * sC;
        #pragma unroll
        for (int i = 0; i < 4; i++) {
            const int j0 = bm + wm * 64 + i * 16 + (lane >> 2);
            const int j1 = j0 + 8;
            #pragma unroll
            for (int j = 0; j < 8; j++) {
                const int c = bn + wn * 64 + j * 8 + ((lane & 3) << 1);
                if (j0 < nb)
                    *(float2*)&Cfz[(size_t)j0 * ldc + c] =
                        make_float2(acc[i][j][0] * SCALE_QK, acc[i][j][1] * SCALE_QK);
                if (j1 < nb)
                    *(float2*)&Cfz[(size_t)j1 * ldc + c] =
                        make_float2(acc[i][j][2] * SCALE_QK, acc[i][j][3] * SCALE_QK);
            }
        }
    } else if (MODE == 2) {                /* compact qkv routing */
        const int seg = bn / HID;
        fp16* dst = (seg == 0) ? Ch : (seg == 1) ? Ch2 : Ch3;
        const float* bs = (seg == 0) ? bias : (seg == 1) ? bias2 : bias3;
        const int cb = bn - seg * HID;
        const int dorelu = (seg < 2);
        #pragma unroll
        for (int i = 0; i < 4; i++) {
            const int j0 = bm + wm * 64 + i * 16 + (lane >> 2);
            const int j1 = j0 + 8;
            #pragma unroll
            for (int j = 0; j < 8; j++) {
                const int cl = cb + wn * 64 + j * 8 + ((lane & 3) << 1);
                const float b0v = bs[cl], b1v = bs[cl + 1];
                float ax = acc[i][j][0] + b0v, ay = acc[i][j][1] + b1v;
                float az = acc[i][j][2] + b0v, aw = acc[i][j][3] + b1v;
                if (dorelu) {
                    ax = fmaxf(ax, 0.f); ay = fmaxf(ay, 0.f);
                    az = fmaxf(az, 0.f); aw = fmaxf(aw, 0.f);
                }
                if (j0 < nb)
                    *(uint32_t*)((char*)dst + (((size_t)z * SEQ + j0) * HID + cl) * 2) =
                        pack_h2(ax, ay);
                if (j1 < nb)
                    *(uint32_t*)((char*)dst + (((size_t)z * SEQ + j1) * HID + cl) * 2) =
                        pack_h2(az, aw);
            }
        }
    } else {                               /* MODE 3: compact generic */
        const fp16* rz = resh ? (resh + z * sC) : (const fp16*)0;
        fp16* Chz = Ch ? (Ch + z * sC) : (fp16*)0;
        #pragma unroll
        for (int i = 0; i < 4; i++) {
            const int j0 = bm + wm * 64 + i * 16 + (lane >> 2);
            const int j1 = j0 + 8;
            const int ok0 = (j0 < nb), ok1 = (j1 < nb);
            const int s0 = (Cf && ok0) ? __ldg(gidx + z * SEQ + j0) : 0;
            const int s1 = (Cf && ok1) ? __ldg(gidx + z * SEQ + j1) : 0;
            #pragma unroll
            for (int j = 0; j < 8; j++) {
                const int c = bn + wn * 64 + j * 8 + ((lane & 3) << 1);
                float ax = acc[i][j][0], ay = acc[i][j][1];
                float az = acc[i][j][2], aw = acc[i][j][3];
                if (bias) {
                    const float b0v = bias[c], b1v = bias[c + 1];
                    ax += b0v; ay += b1v; az += b0v; aw += b1v;
                }
                if (relu) {
                    ax = fmaxf(ax, 0.f); ay = fmaxf(ay, 0.f);
                    az = fmaxf(az, 0.f); aw = fmaxf(aw, 0.f);
                }
                if (rz) {
                    if (ok0) {
                        const __half2 q0 = *(const __half2*)((const char*)rz +
                            ((size_t)j0 * ldc + c) * 2);
                        const float2 f0 = __half22float2(q0);
                        ax += f0.x; ay += f0.y;
                    }
                    if (ok1) {
                        const __half2 q1 = *(const __half2*)((const char*)rz +
                            ((size_t)j1 * ldc + c) * 2);
                        const float2 f1 = __half22float2(q1);
                        az += f1.x; aw += f1.y;
                    }
                }
                if (Chz) {
                    if (ok0)
                        *(uint32_t*)((char*)Chz + ((size_t)j0 * ldc + c) * 2) = pack_h2(ax, ay);
                    if (ok1)
                        *(uint32_t*)((char*)Chz + ((size_t)j1 * ldc + c) * 2) = pack_h2(az, aw);
                }
                if (Cf) {
                    if (ok0)
                        *(float2*)&Cf[((size_t)z * SEQ + s0) * HID + c] = make_float2(ax, ay);
                    if (ok1)
                        *(float2*)&Cf[((size_t)z * SEQ + s1) * HID + c] = make_float2(az, aw);
                }
            }
        }
    }
}

/* ---- compact softmax: fp32 scores in, fp16 weights out (K zero-padded) ---- */
__global__ __launch_bounds__(256) void softmax_c_kernel(
    const float* __restrict__ Sc, fp16* __restrict__ Wout,
    const int* __restrict__ cnt)
{
    const int b = blockIdx.y, j = blockIdx.x, tid = threadIdx.x;
    const int nb = cnt[b];
    if (j >= nb) return;
    const float* srow = Sc + ((size_t)b * SEQ + j) * SEQ;

    float e[4];
    float mx = -3.0e38f;
    for (int t = tid; t < nb; t += 256) mx = fmaxf(mx, srow[t]);
    #pragma unroll
    for (int o = 16; o > 0; o >>= 1) mx = fmaxf(mx, __shfl_xor_sync(~0u, mx, o));
    __shared__ float red[8];
    if ((tid & 31) == 0) red[tid >> 5] = mx;
    __syncthreads();
    float rmx = red[0];
    #pragma unroll
    for (int i = 1; i < 8; i++) rmx = fmaxf(rmx, red[i]);

    float s = 0.f;
    {
        int i = 0;
        for (int t = tid; t < nb; t += 256, i++) {
            e[i] = expf(srow[t] - rmx);
            s += e[i];
        }
    }
    #pragma unroll
    for (int o = 16; o > 0; o >>= 1) s += __shfl_xor_sync(~0u, s, o);
    __syncthreads();
    if ((tid & 31) == 0) red[tid >> 5] = s;
    __syncthreads();
    float tot = red[0];
    #pragma unroll
    for (int i = 1; i < 8; i++) tot += red[i];
    const float inv = 1.0f / tot;

    const int pad = (nb + 31) & ~31;
    fp16* wrow = Wout + ((size_t)b * SEQ + j) * SEQ;
    {
        int i = 0;
        for (int t = tid; t < pad; t += 256, i++) {
            float v = (t < nb) ? e[i] * inv : 0.f;
            wrow[t] = __float2half_rn(v);
        }
    }
}

/* --------------------------------------------------------------------- */
extern "C" void kernel_launch(void* const* d_in, const int* in_sizes, int n_in,
                              void* d_out, int out_size)
{
    const float* x    = (const float*)d_in[0];
    const int*   mask = (const int*)  d_in[1];
    const float* Wq = (const float*)d_in[2];
    const float* bq = (const float*)d_in[3];
    const float* Wk = (const float*)d_in[4];
    const float* bk = (const float*)d_in[5];
    const float* Wv = (const float*)d_in[6];
    const float* bv = (const float*)d_in[7];
    const float* W1 = (const float*)d_in[8];
    const float* b1 = (const float*)d_in[9];
    const float* W2 = (const float*)d_in[10];
    const float* b2 = (const float*)d_in[11];
    float* out = (float*)d_out;

    fp16 *xc,*qh,*kh,*vh,*oc,*h1h,*wqkv,*w1h,*w2h,*wh;
    float *sc, *cvec; int *gidx, *cnt;
    cudaGetSymbolAddress((void**)&xc,   g_xc);
    cudaGetSymbolAddress((void**)&qh,   g_q);
    cudaGetSymbolAddress((void**)&kh,   g_k);
    cudaGetSymbolAddress((void**)&vh,   g_v);
    cudaGetSymbolAddress((void**)&oc,   g_oc);
    cudaGetSymbolAddress((void**)&h1h,  g_h1);
    cudaGetSymbolAddress((void**)&wqkv, g_wqkv);
    cudaGetSymbolAddress((void**)&w1h,  g_w1);
    cudaGetSymbolAddress((void**)&w2h,  g_w2);
    cudaGetSymbolAddress((void**)&wh,   g_w);
    cudaGetSymbolAddress((void**)&sc,   g_sc);
    cudaGetSymbolAddress((void**)&gidx, g_idx);
    cudaGetSymbolAddress((void**)&cnt,  g_cnt);
    cudaGetSymbolAddress((void**)&cvec, g_cvec);

    cudaFuncSetAttribute(gemm_fp16<0,1>, cudaFuncAttributeMaxDynamicSharedMemorySize, SMEM_GEMM);
    cudaFuncSetAttribute(gemm_fp16<0,2>, cudaFuncAttributeMaxDynamicSharedMemorySize, SMEM_GEMM);
    cudaFuncSetAttribute(gemm_fp16<1,3>, cudaFuncAttributeMaxDynamicSharedMemorySize, SMEM_GEMM);
    cudaFuncSetAttribute(gemm_fp16<0,3>, cudaFuncAttributeMaxDynamicSharedMemorySize, SMEM_GEMM);

    dim3 blk(NTHREADS);
    const size_t sBH = (size_t)SEQ * HID, sBS = (size_t)SEQ * SEQ;
    dim3 gqkv(3 * HID / BN, SEQ / BM, NB);        /* (18, 8, 16) compact-M */
    dim3 gsc(SEQ / BN, SEQ / BM, NB);             /* (8, 8, 16) compact-MN */
    dim3 gpv(HID / BN, SEQ / BM, NB);             /* (6, 8, 16) compact-M, var-K */
    dim3 gffn(HID / BN, SEQ / BM, NB);            /* (6, 8, 16) compact-M */

    idx_kernel<<<NB, 32>>>(mask, gidx, cnt);                                       /* 0 */
    cvt_w3_kernel<<<dim3((NWE/2 + 255)/256, 3), 256>>>(Wq, Wk, Wv,
        (uint32_t*)wqkv, NWE/2);                                                   /* 1 */
    gather_x_kernel<<<dim3(SEQ, NB), 192>>>(x, gidx, cnt, (uint32_t*)xc);          /* 2 */
    cvt_w2_kernel<<<dim3((NWE/2 + 255)/256, 2), 256>>>(W1, W2,
        (uint32_t*)w1h, (uint32_t*)w2h, NWE/2);                                    /* 3 */
    cvec_kernel<<<HID/128, 128>>>(b1, W2, b2, cvec);                               /* 4 */

    /* fused compact q,k,v projection (launch index 5 — profiled) */
    gemm_fp16<0,2><<<gqkv, blk, SMEM_GEMM>>>(xc, wqkv, HID, HID, 0, sBH, 0, 0,
        nullptr, qh, kh, vh, HID, bq, bk, bv, nullptr, cnt, gidx, 0);              /* 5 */

    /* compact scores */
    gemm_fp16<0,1><<<gsc, blk, SMEM_GEMM>>>(qh, kh, HID, HID, 0, sBH, sBH, sBS,
        sc, nullptr, nullptr, nullptr, SEQ, nullptr, nullptr, nullptr,
        nullptr, cnt, gidx, 0);                                                    /* 6 */

    softmax_c_kernel<<<dim3(SEQ, NB), 256>>>(sc, wh, cnt);                         /* 7 */

    /* compact PV -> compact o */
    gemm_fp16<1,3><<<gpv, blk, SMEM_GEMM>>>(wh, vh, SEQ, SEQ, HID, sBS, sBH, sBH,
        nullptr, oc, nullptr, nullptr, HID, nullptr, nullptr, nullptr,
        nullptr, cnt, gidx, 0);                                                    /* 8 */

    fill_masked_kernel<<<dim3(SEQ, NB), 192>>>(mask, cvec, out);                   /* 9 */

    /* compact FFN */
    gemm_fp16<0,3><<<gffn, blk, SMEM_GEMM>>>(oc, w1h, HID, HID, 0, sBH, 0, sBH,
        nullptr, h1h, nullptr, nullptr, HID, b1, nullptr, nullptr,
        nullptr, cnt, gidx, 1);                                                    /* 10 */
    gemm_fp16<0,3><<<gffn, blk, SMEM_GEMM>>>(h1h, w2h, HID, HID, 0, sBH, 0, sBH,
        out, nullptr, nullptr, nullptr, HID, b2, nullptr, nullptr,
        oc, cnt, gidx, 0);                                                         /* 11 */
}

// round 15
// speedup vs baseline: 1.1454x; 1.1454x over previous
#include <cuda_runtime.h>
#include <cuda_fp16.h>
#include <cstdint>

#define NB   16
#define SEQ  1024
#define HID  768
#define SCALE_QK 0.03608439182435161f

#define BM 128
#define BN 128
#define BK 32
#define NTHREADS 128
#define STG 10240            /* one operand tile: 128 rows * 80B */
#define STAGE_BYTES 20480    /* A + B */
#define NSTAGES 4
#define SMEM_GEMM (NSTAGES*STAGE_BYTES)   /* 80 KB -> 2 CTAs/SM */

typedef __half fp16;

/* ------------------ scratch (device globals, zero-initialized) ------------ */
#define NXE 12582912   /* 16*1024*768 */
#define NWE 589824     /* 768*768 */
#define NSE 16777216   /* 16*1024*1024 */
__device__ fp16 g_xc[NXE];                 /* compacted x rows (fp16) */
__device__ fp16 g_q [NXE];                 /* compact q */
__device__ fp16 g_k [NXE];                 /* compact k */
__device__ fp16 g_v [NXE];                 /* compact v */
__device__ fp16 g_oc[NXE];                 /* compact attention out */
__device__ fp16 g_h1[NXE];                 /* compact ffn hidden */
__device__ fp16 g_wqkv[3*NWE];
__device__ fp16 g_w1[NWE], g_w2[NWE];
__device__ float g_sc[NSE];                /* compact scores, ld=1024 */
__device__ fp16 g_w [NSE];                 /* compact softmax weights, K zero-padded */
__device__ int  g_idx[NB*SEQ];
__device__ int  g_cnt[NB];
__device__ float g_cvec[HID];              /* constant out row for masked rows */

/* ------------------ helpers ------------------ */
static __device__ __forceinline__ uint32_t smem_u32(const void* p) {
    uint32_t a;
    asm("{ .reg .u64 t; cvta.to.shared.u64 t, %1; cvt.u32.u64 %0, t; }" : "=r"(a) : "l"(p));
    return a;
}
static __device__ __forceinline__ uint32_t pack_h2(float v0, float v1) {
    __half2 h = __floats2half2_rn(v0, v1);
    return *reinterpret_cast<uint32_t*>(&h);
}

#define CP16(dst, src) \
    asm volatile("cp.async.cg.shared.global [%0], [%1], 16;" :: "r"(dst), "l"(src))
#define CPCOMMIT() asm volatile("cp.async.commit_group;" ::: "memory")
#define CPWAIT2()  asm volatile("cp.async.wait_group 2;" ::: "memory")

#define LDSM4(r, a) \
    asm volatile("ldmatrix.sync.aligned.m8n8.x4.shared.b16 {%0,%1,%2,%3}, [%4];" \
        : "=r"((r)[0]),"=r"((r)[1]),"=r"((r)[2]),"=r"((r)[3]) : "r"(a))
#define LDSM4T(r, a) \
    asm volatile("ldmatrix.sync.aligned.m8n8.x4.trans.shared.b16 {%0,%1,%2,%3}, [%4];" \
        : "=r"((r)[0]),"=r"((r)[1]),"=r"((r)[2]),"=r"((r)[3]) : "r"(a))
#define MMA(c, a, b0, b1) \
    asm volatile("mma.sync.aligned.m16n8k16.row.col.f32.f16.f16.f32 " \
        "{%0,%1,%2,%3}, {%4,%5,%6,%7}, {%8,%9}, {%0,%1,%2,%3};" \
        : "+f"((c)[0]), "+f"((c)[1]), "+f"((c)[2]), "+f"((c)[3]) \
        : "r"((a)[0]),"r"((a)[1]),"r"((a)[2]),"r"((a)[3]), "r"(b0), "r"(b1))

/* ---- per-batch compaction index (1 warp per batch, ballot scan) ---- */
__global__ __launch_bounds__(32) void idx_kernel(
    const int* __restrict__ mask, int* __restrict__ gidx, int* __restrict__ cnt)
{
    const int b = blockIdx.x, lane = threadIdx.x;
    int c = 0;
    for (int s0 = 0; s0 < SEQ; s0 += 32) {
        const int v = mask[b * SEQ + s0 + lane];
        const unsigned bal = __ballot_sync(~0u, v != 0);
        const int pos = c + __popc(bal & ((1u << lane) - 1u));
        if (v) gidx[b * SEQ + pos] = s0 + lane;
        c += __popc(bal);
    }
    if (lane == 0) cnt[b] = c;
}

/* ---- gather + fp32->fp16 convert compacted x rows ---- */
__global__ __launch_bounds__(192) void gather_x_kernel(
    const float* __restrict__ x, const int* __restrict__ gidx,
    const int* __restrict__ cnt, uint32_t* __restrict__ xc)
{
    const int j = blockIdx.x, b = blockIdx.y, t = threadIdx.x;
    if (j >= cnt[b]) return;
    const int s = gidx[b * SEQ + j];
    const float4 v = reinterpret_cast<const float4*>(x + ((size_t)b * SEQ + s) * HID)[t];
    uint2 o;
    o.x = pack_h2(v.x, v.y);
    o.y = pack_h2(v.z, v.w);
    reinterpret_cast<uint2*>(xc + ((size_t)b * SEQ + j) * (HID / 2))[t] = o;
}

/* ---- weight converts ---- */
__global__ __launch_bounds__(256) void cvt_w3_kernel(
    const float* __restrict__ s0, const float* __restrict__ s1,
    const float* __restrict__ s2, uint32_t* __restrict__ wqkv, int n2)
{
    int i = blockIdx.x * 256 + threadIdx.x;
    if (i >= n2) return;
    const int y = blockIdx.y;
    const float* s = (y == 0) ? s0 : (y == 1) ? s1 : s2;
    float2 v = reinterpret_cast<const float2*>(s)[i];
    wqkv[(size_t)y * n2 + i] = pack_h2(v.x, v.y);
}
__global__ __launch_bounds__(256) void cvt_w2_kernel(
    const float* __restrict__ s0, const float* __restrict__ s1,
    uint32_t* __restrict__ w1, uint32_t* __restrict__ w2, int n2)
{
    int i = blockIdx.x * 256 + threadIdx.x;
    if (i >= n2) return;
    const float* s = blockIdx.y ? s1 : s0;
    uint32_t* d = blockIdx.y ? w2 : w1;
    float2 v = reinterpret_cast<const float2*>(s)[i];
    d[i] = pack_h2(v.x, v.y);
}

/* ---- constant masked-row output: cvec[o] = relu(b1) . W2[o,:] + b2[o]
   One block per output element, 256-thread reduction (exact fp32). ---- */
__global__ __launch_bounds__(256) void cvec_kernel(
    const float* __restrict__ b1, const float* __restrict__ W2,
    const float* __restrict__ b2, float* __restrict__ cvec)
{
    const int o = blockIdx.x, tid = threadIdx.x;
    const float* w = W2 + (size_t)o * HID;
    float s = 0.f;
    for (int h = tid; h < HID; h += 256)
        s = fmaf(fmaxf(b1[h], 0.f), w[h], s);
    #pragma unroll
    for (int i = 16; i > 0; i >>= 1) s += __shfl_xor_sync(~0u, s, i);
    __shared__ float red[8];
    if ((tid & 31) == 0) red[tid >> 5] = s;
    __syncthreads();
    if (tid == 0) {
        float tot = b2[o];
        #pragma unroll
        for (int i = 0; i < 8; i++) tot += red[i];
        cvec[o] = tot;
    }
}

/* ---- fill masked rows of the dense output with cvec ---- */
__global__ __launch_bounds__(192) void fill_masked_kernel(
    const int* __restrict__ mask, const float* __restrict__ cvec,
    float* __restrict__ out)
{
    const int s = blockIdx.x, b = blockIdx.y, t = threadIdx.x;
    if (mask[b * SEQ + s]) return;
    const float4 v = reinterpret_cast<const float4*>(cvec)[t];
    reinterpret_cast<float4*>(out + ((size_t)b * SEQ + s) * HID)[t] = v;
}

/* ---------------------------------------------------------------------------
 * fp16 GEMM, mma.sync m16n8k16, fp32 acc. CTA 128x128xBK32, warp tile 64x64,
 * 4-stage cp.async, 2 CTAs/SM. All compact-M (guarded by cnt[z]).
 * NN=0: C=A*B^T (K-major); NN=1: C=A*B (B N-major, ldbn row stride).
 * MODE 1: scores: M,N guarded; fp32 out (ld 1024), *SCALE.
 * MODE 2: fused qkv: N spans 3 HID segments -> q/k/v, relu on segs 0,1.
 * MODE 3: compact generic: bias/relu opt, resh compact fp16 residual opt,
 *         Ch compact fp16 out opt, Cf = DENSE fp32 out scattered via gidx opt.
 *         If NN==1, K = pad32(cnt[z]) (PV case).
 * ------------------------------------------------------------------------ */
template<int NN, int MODE>
__global__ __launch_bounds__(NTHREADS, 2) void gemm_fp16(
    const fp16* __restrict__ A, const fp16* __restrict__ B,
    int K, int lda, int ldbn,
    size_t sA, size_t sB, size_t sC,
    float* __restrict__ Cf, fp16* __restrict__ Ch,
    fp16* __restrict__ Ch2, fp16* __restrict__ Ch3,
    int ldc,
    const float* __restrict__ bias, const float* __restrict__ bias2,
    const float* __restrict__ bias3,
    const fp16* __restrict__ resh,
    const int* __restrict__ cnt, const int* __restrict__ gidx, int relu)
{
    extern __shared__ char smraw[];
    const uint32_t sb = smem_u32(smraw);
    const int tid = threadIdx.x, lane = tid & 31, wid = tid >> 5;
    const int wm = wid & 1, wn = wid >> 1;
    const int z = blockIdx.z, bm = blockIdx.y * BM, bn = blockIdx.x * BN;

    const int nb = __ldg(cnt + z);
    if (bm >= nb) return;
    if (MODE == 1 && bn >= nb) return;
    if (MODE == 3 && NN == 1) K = (nb + 31) & ~31;

    const fp16* Ag = A + z * sA + (size_t)bm * lda;
    const fp16* Bg;
    if (NN) Bg = B + z * sB + bn;
    else    Bg = B + z * sB + (size_t)bn * K;

    float acc[4][8][4];
    #pragma unroll
    for (int i = 0; i < 4; i++)
        #pragma unroll
        for (int j = 0; j < 8; j++)
            #pragma unroll
            for (int t = 0; t < 4; t++) acc[i][j][t] = 0.f;

    auto issue = [&](int s) {
        const uint32_t stb = sb + (uint32_t)(s % NSTAGES) * STAGE_BYTES;
        const int k0 = s * BK;
        #pragma unroll
        for (int i = 0; i < 4; i++) {
            const int idx = tid + (i << 7);
            const int row = idx >> 2, c8 = (idx & 3) << 3;
            CP16(stb + row * 80 + (c8 << 1), Ag + (size_t)row * lda + k0 + c8);
        }
        if (!NN) {
            #pragma unroll
            for (int i = 0; i < 4; i++) {
                const int idx = tid + (i << 7);
                const int row = idx >> 2, c8 = (idx & 3) << 3;
                CP16(stb + STG + row * 80 + (c8 << 1), Bg + (size_t)row * K + k0 + c8);
            }
        } else {
            #pragma unroll
            for (int i = 0; i < 4; i++) {
                const int idx = tid + (i << 7);
                const int row = idx >> 4, c8 = (idx & 15) << 3;
                CP16(stb + STG + row * 272 + (c8 << 1), Bg + (size_t)(k0 + row) * ldbn + c8);
            }
        }
    };

    auto compute = [&](int s) {
        const uint32_t stb = sb + (uint32_t)(s % NSTAGES) * STAGE_BYTES;
        #pragma unroll
        for (int ks = 0; ks < 2; ks++) {
            uint32_t ah[4][4];
            #pragma unroll
            for (int i = 0; i < 4; i++) {
                const int arow = wm * 64 + i * 16 + (lane & 15);
                LDSM4(ah[i], stb + arow * 80 + ((ks * 16 + ((lane >> 4) << 3)) << 1));
            }
            #pragma unroll
            for (int p = 0; p < 4; p++) {
                uint32_t bh[4];
                if (!NN) {
                    const int brow = wn * 64 + p * 16 + (lane & 7) + ((lane >> 4) << 3);
                    LDSM4(bh, stb + STG + brow * 80 +
                              ((ks * 16 + (((lane >> 3) & 1) << 3)) << 1));
                } else {
                    const int krow = ks * 16 + (lane & 7) + (((lane >> 3) & 1) << 3);
                    const int ncol = wn * 64 + p * 16 + ((lane >> 4) << 3);
                    LDSM4T(bh, stb + STG + krow * 272 + (ncol << 1));
                }
                #pragma unroll
                for (int i = 0; i < 4; i++)
                    #pragma unroll
                    for (int jj = 0; jj < 2; jj++)
                        MMA(acc[i][p * 2 + jj], ah[i], bh[jj * 2], bh[jj * 2 + 1]);
            }
        }
    };

    const int NSt = K / BK;
    issue(0); CPCOMMIT();
    if (NSt > 1) issue(1); CPCOMMIT();
    if (NSt > 2) issue(2); CPCOMMIT();
    for (int s = 0; s < NSt; s++) {
        CPWAIT2();
        __syncthreads();
        if (s + 3 < NSt) issue(s + 3);
        CPCOMMIT();
        compute(s);
    }

    /* ---- epilogue ---- */
    if (MODE == 1) {                       /* compact scores, fp32 */
        float* Cfz = Cf + (size_t)z * sC;
        #pragma unroll
        for (int i = 0; i < 4; i++) {
            const int j0 = bm + wm * 64 + i * 16 + (lane >> 2);
            const int j1 = j0 + 8;
            #pragma unroll
            for (int j = 0; j < 8; j++) {
                const int c = bn + wn * 64 + j * 8 + ((lane & 3) << 1);
                if (j0 < nb)
                    *(float2*)&Cfz[(size_t)j0 * ldc + c] =
                        make_float2(acc[i][j][0] * SCALE_QK, acc[i][j][1] * SCALE_QK);
                if (j1 < nb)
                    *(float2*)&Cfz[(size_t)j1 * ldc + c] =
                        make_float2(acc[i][j][2] * SCALE_QK, acc[i][j][3] * SCALE_QK);
            }
        }
    } else if (MODE == 2) {                /* compact qkv routing */
        const int seg = bn / HID;
        fp16* dst = (seg == 0) ? Ch : (seg == 1) ? Ch2 : Ch3;
        const float* bs = (seg == 0) ? bias : (seg == 1) ? bias2 : bias3;
        const int cb = bn - seg * HID;
        const int dorelu = (seg < 2);
        #pragma unroll
        for (int i = 0; i < 4; i++) {
            const int j0 = bm + wm * 64 + i * 16 + (lane >> 2);
            const int j1 = j0 + 8;
            #pragma unroll
            for (int j = 0; j < 8; j++) {
                const int cl = cb + wn * 64 + j * 8 + ((lane & 3) << 1);
                const float b0v = bs[cl], b1v = bs[cl + 1];
                float ax = acc[i][j][0] + b0v, ay = acc[i][j][1] + b1v;
                float az = acc[i][j][2] + b0v, aw = acc[i][j][3] + b1v;
                if (dorelu) {
                    ax = fmaxf(ax, 0.f); ay = fmaxf(ay, 0.f);
                    az = fmaxf(az, 0.f); aw = fmaxf(aw, 0.f);
                }
                if (j0 < nb)
                    *(uint32_t*)((char*)dst + (((size_t)z * SEQ + j0) * HID + cl) * 2) =
                        pack_h2(ax, ay);
                if (j1 < nb)
                    *(uint32_t*)((char*)dst + (((size_t)z * SEQ + j1) * HID + cl) * 2) =
                        pack_h2(az, aw);
            }
        }
    } else {                               /* MODE 3: compact generic */
        const fp16* rz = resh ? (resh + z * sC) : (const fp16*)0;
        fp16* Chz = Ch ? (Ch + z * sC) : (fp16*)0;
        #pragma unroll
        for (int i = 0; i < 4; i++) {
            const int j0 = bm + wm * 64 + i * 16 + (lane >> 2);
            const int j1 = j0 + 8;
            const int ok0 = (j0 < nb), ok1 = (j1 < nb);
            const int s0 = (Cf && ok0) ? __ldg(gidx + z * SEQ + j0) : 0;
            const int s1 = (Cf && ok1) ? __ldg(gidx + z * SEQ + j1) : 0;
            #pragma unroll
            for (int j = 0; j < 8; j++) {
                const int c = bn + wn * 64 + j * 8 + ((lane & 3) << 1);
                float ax = acc[i][j][0], ay = acc[i][j][1];
                float az = acc[i][j][2], aw = acc[i][j][3];
                if (bias) {
                    const float b0v = bias[c], b1v = bias[c + 1];
                    ax += b0v; ay += b1v; az += b0v; aw += b1v;
                }
                if (relu) {
                    ax = fmaxf(ax, 0.f); ay = fmaxf(ay, 0.f);
                    az = fmaxf(az, 0.f); aw = fmaxf(aw, 0.f);
                }
                if (rz) {
                    if (ok0) {
                        const __half2 q0 = *(const __half2*)((const char*)rz +
                            ((size_t)j0 * ldc + c) * 2);
                        const float2 f0 = __half22float2(q0);
                        ax += f0.x; ay += f0.y;
                    }
                    if (ok1) {
                        const __half2 q1 = *(const __half2*)((const char*)rz +
                            ((size_t)j1 * ldc + c) * 2);
                        const float2 f1 = __half22float2(q1);
                        az += f1.x; aw += f1.y;
                    }
                }
                if (Chz) {
                    if (ok0)
                        *(uint32_t*)((char*)Chz + ((size_t)j0 * ldc + c) * 2) = pack_h2(ax, ay);
                    if (ok1)
                        *(uint32_t*)((char*)Chz + ((size_t)j1 * ldc + c) * 2) = pack_h2(az, aw);
                }
                if (Cf) {
                    if (ok0)
                        *(float2*)&Cf[((size_t)z * SEQ + s0) * HID + c] = make_float2(ax, ay);
                    if (ok1)
                        *(float2*)&Cf[((size_t)z * SEQ + s1) * HID + c] = make_float2(az, aw);
                }
            }
        }
    }
}

/* ---- compact softmax: fp32 scores in, fp16 weights out (K zero-padded) ---- */
__global__ __launch_bounds__(256) void softmax_c_kernel(
    const float* __restrict__ Sc, fp16* __restrict__ Wout,
    const int* __restrict__ cnt)
{
    const int b = blockIdx.y, j = blockIdx.x, tid = threadIdx.x;
    const int nb = cnt[b];
    if (j >= nb) return;
    const float* srow = Sc + ((size_t)b * SEQ + j) * SEQ;

    float e[4];
    float mx = -3.0e38f;
    for (int t = tid; t < nb; t += 256) mx = fmaxf(mx, srow[t]);
    #pragma unroll
    for (int o = 16; o > 0; o >>= 1) mx = fmaxf(mx, __shfl_xor_sync(~0u, mx, o));
    __shared__ float red[8];
    if ((tid & 31) == 0) red[tid >> 5] = mx;
    __syncthreads();
    float rmx = red[0];
    #pragma unroll
    for (int i = 1; i < 8; i++) rmx = fmaxf(rmx, red[i]);

    float s = 0.f;
    {
        int i = 0;
        for (int t = tid; t < nb; t += 256, i++) {
            e[i] = expf(srow[t] - rmx);
            s += e[i];
        }
    }
    #pragma unroll
    for (int o = 16; o > 0; o >>= 1) s += __shfl_xor_sync(~0u, s, o);
    __syncthreads();
    if ((tid & 31) == 0) red[tid >> 5] = s;
    __syncthreads();
    float tot = red[0];
    #pragma unroll
    for (int i = 1; i < 8; i++) tot += red[i];
    const float inv = 1.0f / tot;

    const int pad = (nb + 31) & ~31;
    fp16* wrow = Wout + ((size_t)b * SEQ + j) * SEQ;
    {
        int i = 0;
        for (int t = tid; t < pad; t += 256, i++) {
            float v = (t < nb) ? e[i] * inv : 0.f;
            wrow[t] = __float2half_rn(v);
        }
    }
}

/* --------------------------------------------------------------------- */
extern "C" void kernel_launch(void* const* d_in, const int* in_sizes, int n_in,
                              void* d_out, int out_size)
{
    const float* x    = (const float*)d_in[0];
    const int*   mask = (const int*)  d_in[1];
    const float* Wq = (const float*)d_in[2];
    const float* bq = (const float*)d_in[3];
    const float* Wk = (const float*)d_in[4];
    const float* bk = (const float*)d_in[5];
    const float* Wv = (const float*)d_in[6];
    const float* bv = (const float*)d_in[7];
    const float* W1 = (const float*)d_in[8];
    const float* b1 = (const float*)d_in[9];
    const float* W2 = (const float*)d_in[10];
    const float* b2 = (const float*)d_in[11];
    float* out = (float*)d_out;

    fp16 *xc,*qh,*kh,*vh,*oc,*h1h,*wqkv,*w1h,*w2h,*wh;
    float *sc, *cvec; int *gidx, *cnt;
    cudaGetSymbolAddress((void**)&xc,   g_xc);
    cudaGetSymbolAddress((void**)&qh,   g_q);
    cudaGetSymbolAddress((void**)&kh,   g_k);
    cudaGetSymbolAddress((void**)&vh,   g_v);
    cudaGetSymbolAddress((void**)&oc,   g_oc);
    cudaGetSymbolAddress((void**)&h1h,  g_h1);
    cudaGetSymbolAddress((void**)&wqkv, g_wqkv);
    cudaGetSymbolAddress((void**)&w1h,  g_w1);
    cudaGetSymbolAddress((void**)&w2h,  g_w2);
    cudaGetSymbolAddress((void**)&wh,   g_w);
    cudaGetSymbolAddress((void**)&sc,   g_sc);
    cudaGetSymbolAddress((void**)&gidx, g_idx);
    cudaGetSymbolAddress((void**)&cnt,  g_cnt);
    cudaGetSymbolAddress((void**)&cvec, g_cvec);

    cudaFuncSetAttribute(gemm_fp16<0,1>, cudaFuncAttributeMaxDynamicSharedMemorySize, SMEM_GEMM);
    cudaFuncSetAttribute(gemm_fp16<0,2>, cudaFuncAttributeMaxDynamicSharedMemorySize, SMEM_GEMM);
    cudaFuncSetAttribute(gemm_fp16<1,3>, cudaFuncAttributeMaxDynamicSharedMemorySize, SMEM_GEMM);
    cudaFuncSetAttribute(gemm_fp16<0,3>, cudaFuncAttributeMaxDynamicSharedMemorySize, SMEM_GEMM);

    dim3 blk(NTHREADS);
    const size_t sBH = (size_t)SEQ * HID, sBS = (size_t)SEQ * SEQ;
    dim3 gqkv(3 * HID / BN, SEQ / BM, NB);        /* (18, 8, 16) compact-M */
    dim3 gsc(SEQ / BN, SEQ / BM, NB);             /* (8, 8, 16) compact-MN */
    dim3 gpv(HID / BN, SEQ / BM, NB);             /* (6, 8, 16) compact-M, var-K */
    dim3 gffn(HID / BN, SEQ / BM, NB);            /* (6, 8, 16) compact-M */

    idx_kernel<<<NB, 32>>>(mask, gidx, cnt);                                       /* 0 */
    cvt_w3_kernel<<<dim3((NWE/2 + 255)/256, 3), 256>>>(Wq, Wk, Wv,
        (uint32_t*)wqkv, NWE/2);                                                   /* 1 */
    gather_x_kernel<<<dim3(SEQ, NB), 192>>>(x, gidx, cnt, (uint32_t*)xc);          /* 2 */
    cvt_w2_kernel<<<dim3((NWE/2 + 255)/256, 2), 256>>>(W1, W2,
        (uint32_t*)w1h, (uint32_t*)w2h, NWE/2);                                    /* 3 */
    cvec_kernel<<<HID, 256>>>(b1, W2, b2, cvec);                                   /* 4 */

    /* fused compact q,k,v projection (launch index 5 — profiled) */
    gemm_fp16<0,2><<<gqkv, blk, SMEM_GEMM>>>(xc, wqkv, HID, HID, 0, sBH, 0, 0,
        nullptr, qh, kh, vh, HID, bq, bk, bv, nullptr, cnt, gidx, 0);              /* 5 */

    /* compact scores */
    gemm_fp16<0,1><<<gsc, blk, SMEM_GEMM>>>(qh, kh, HID, HID, 0, sBH, sBH, sBS,
        sc, nullptr, nullptr, nullptr, SEQ, nullptr, nullptr, nullptr,
        nullptr, cnt, gidx, 0);                                                    /* 6 */

    softmax_c_kernel<<<dim3(SEQ, NB), 256>>>(sc, wh, cnt);                         /* 7 */

    /* compact PV -> compact o */
    gemm_fp16<1,3><<<gpv, blk, SMEM_GEMM>>>(wh, vh, SEQ, SEQ, HID, sBS, sBH, sBH,
        nullptr, oc, nullptr, nullptr, HID, nullptr, nullptr, nullptr,
        nullptr, cnt, gidx, 0);                                                    /* 8 */

    fill_masked_kernel<<<dim3(SEQ, NB), 192>>>(mask, cvec, out);                   /* 9 */

    /* compact FFN */
    gemm_fp16<0,3><<<gffn, blk, SMEM_GEMM>>>(oc, w1h, HID, HID, 0, sBH, 0, sBH,
        nullptr, h1h, nullptr, nullptr, HID, b1, nullptr, nullptr,
        nullptr, cnt, gidx, 1);                                                    /* 10 */
    gemm_fp16<0,3><<<gffn, blk, SMEM_GEMM>>>(h1h, w2h, HID, HID, 0, sBH, 0, sBH,
        out, nullptr, nullptr, nullptr, HID, b2, nullptr, nullptr,
        oc, cnt, gidx, 0);                                                         /* 11 */
}

// round 16
// speedup vs baseline: 1.1792x; 1.0295x over previous
#include <cuda_runtime.h>
#include <cuda_fp16.h>
#include <cstdint>

#define NB   16
#define SEQ  1024
#define HID  768
#define SCALE_QK 0.03608439182435161f

#define BM 128
#define BN 128
#define BK 32
#define NTHREADS 128
#define STG 10240            /* one operand tile: 128 rows * 80B */
#define STAGE_BYTES 20480    /* A + B */
#define NSTAGES 4
#define SMEM_GEMM (NSTAGES*STAGE_BYTES)   /* 80 KB -> 2 CTAs/SM */

typedef __half fp16;

/* ------------------ scratch (device globals, zero-initialized) ------------ */
#define NXE 12582912   /* 16*1024*768 */
#define NWE 589824     /* 768*768 */
#define NSE 16777216   /* 16*1024*1024 */
__device__ fp16 g_xc[NXE];                 /* compacted x rows (fp16) */
__device__ fp16 g_q [NXE];                 /* compact q */
__device__ fp16 g_k [NXE];                 /* compact k */
__device__ fp16 g_v [NXE];                 /* compact v */
__device__ fp16 g_oc[NXE];                 /* compact attention out */
__device__ fp16 g_h1[NXE];                 /* compact ffn hidden */
__device__ fp16 g_wqkv[3*NWE];
__device__ fp16 g_w1[NWE], g_w2[NWE];
__device__ float g_sc[NSE];                /* compact scores, ld=1024 */
__device__ fp16 g_w [NSE];                 /* compact softmax weights, K zero-padded */
__device__ int  g_idx[NB*SEQ];
__device__ int  g_cnt[NB];
__device__ float g_cvec[HID];              /* constant out row for masked rows */

/* ------------------ helpers ------------------ */
static __device__ __forceinline__ uint32_t smem_u32(const void* p) {
    uint32_t a;
    asm("{ .reg .u64 t; cvta.to.shared.u64 t, %1; cvt.u32.u64 %0, t; }" : "=r"(a) : "l"(p));
    return a;
}
static __device__ __forceinline__ uint32_t pack_h2(float v0, float v1) {
    __half2 h = __floats2half2_rn(v0, v1);
    return *reinterpret_cast<uint32_t*>(&h);
}

#define CP16(dst, src) \
    asm volatile("cp.async.cg.shared.global [%0], [%1], 16;" :: "r"(dst), "l"(src))
#define CPCOMMIT() asm volatile("cp.async.commit_group;" ::: "memory")
#define CPWAIT2()  asm volatile("cp.async.wait_group 2;" ::: "memory")

#define LDSM4(r, a) \
    asm volatile("ldmatrix.sync.aligned.m8n8.x4.shared.b16 {%0,%1,%2,%3}, [%4];" \
        : "=r"((r)[0]),"=r"((r)[1]),"=r"((r)[2]),"=r"((r)[3]) : "r"(a))
#define LDSM4T(r, a) \
    asm volatile("ldmatrix.sync.aligned.m8n8.x4.trans.shared.b16 {%0,%1,%2,%3}, [%4];" \
        : "=r"((r)[0]),"=r"((r)[1]),"=r"((r)[2]),"=r"((r)[3]) : "r"(a))
#define MMA(c, a, b0, b1) \
    asm volatile("mma.sync.aligned.m16n8k16.row.col.f32.f16.f16.f32 " \
        "{%0,%1,%2,%3}, {%4,%5,%6,%7}, {%8,%9}, {%0,%1,%2,%3};" \
        : "+f"((c)[0]), "+f"((c)[1]), "+f"((c)[2]), "+f"((c)[3]) \
        : "r"((a)[0]),"r"((a)[1]),"r"((a)[2]),"r"((a)[3]), "r"(b0), "r"(b1))

/* ---- per-batch compaction index (1 warp per batch, ballot scan) ---- */
__global__ __launch_bounds__(32) void idx_kernel(
    const int* __restrict__ mask, int* __restrict__ gidx, int* __restrict__ cnt)
{
    const int b = blockIdx.x, lane = threadIdx.x;
    int c = 0;
    for (int s0 = 0; s0 < SEQ; s0 += 32) {
        const int v = mask[b * SEQ + s0 + lane];
        const unsigned bal = __ballot_sync(~0u, v != 0);
        const int pos = c + __popc(bal & ((1u << lane) - 1u));
        if (v) gidx[b * SEQ + pos] = s0 + lane;
        c += __popc(bal);
    }
    if (lane == 0) cnt[b] = c;
}

/* ---- gather + fp32->fp16 convert compacted x rows ---- */
__global__ __launch_bounds__(192) void gather_x_kernel(
    const float* __restrict__ x, const int* __restrict__ gidx,
    const int* __restrict__ cnt, uint32_t* __restrict__ xc)
{
    const int j = blockIdx.x, b = blockIdx.y, t = threadIdx.x;
    if (j >= cnt[b]) return;
    const int s = gidx[b * SEQ + j];
    const float4 v = reinterpret_cast<const float4*>(x + ((size_t)b * SEQ + s) * HID)[t];
    uint2 o;
    o.x = pack_h2(v.x, v.y);
    o.y = pack_h2(v.z, v.w);
    reinterpret_cast<uint2*>(xc + ((size_t)b * SEQ + j) * (HID / 2))[t] = o;
}

/* ---- all 5 weight converts in one launch (blockIdx.y selects) ---- */
__global__ __launch_bounds__(256) void cvt_w5_kernel(
    const float* __restrict__ s0, const float* __restrict__ s1,
    const float* __restrict__ s2, const float* __restrict__ s3,
    const float* __restrict__ s4,
    uint32_t* __restrict__ wqkv, uint32_t* __restrict__ w1,
    uint32_t* __restrict__ w2, int n2)
{
    int i = blockIdx.x * 256 + threadIdx.x;
    if (i >= n2) return;
    const int y = blockIdx.y;
    const float* s = (y == 0) ? s0 : (y == 1) ? s1 : (y == 2) ? s2 : (y == 3) ? s3 : s4;
    uint32_t* d = (y < 3) ? (wqkv + (size_t)y * n2) : (y == 3) ? w1 : w2;
    float2 v = reinterpret_cast<const float2*>(s)[i];
    d[i] = pack_h2(v.x, v.y);
}

/* ---- constant masked-row output: cvec[o] = relu(b1) . W2[o,:] + b2[o] ---- */
__global__ __launch_bounds__(256) void cvec_kernel(
    const float* __restrict__ b1, const float* __restrict__ W2,
    const float* __restrict__ b2, float* __restrict__ cvec)
{
    const int o = blockIdx.x, tid = threadIdx.x;
    const float* w = W2 + (size_t)o * HID;
    float s = 0.f;
    for (int h = tid; h < HID; h += 256)
        s = fmaf(fmaxf(b1[h], 0.f), w[h], s);
    #pragma unroll
    for (int i = 16; i > 0; i >>= 1) s += __shfl_xor_sync(~0u, s, i);
    __shared__ float red[8];
    if ((tid & 31) == 0) red[tid >> 5] = s;
    __syncthreads();
    if (tid == 0) {
        float tot = b2[o];
        #pragma unroll
        for (int i = 0; i < 8; i++) tot += red[i];
        cvec[o] = tot;
    }
}

/* ---- fill masked rows of the dense output with cvec ---- */
__global__ __launch_bounds__(192) void fill_masked_kernel(
    const int* __restrict__ mask, const float* __restrict__ cvec,
    float* __restrict__ out)
{
    const int s = blockIdx.x, b = blockIdx.y, t = threadIdx.x;
    if (mask[b * SEQ + s]) return;
    const float4 v = reinterpret_cast<const float4*>(cvec)[t];
    reinterpret_cast<float4*>(out + ((size_t)b * SEQ + s) * HID)[t] = v;
}

/* ---------------------------------------------------------------------------
 * fp16 GEMM, mma.sync m16n8k16, fp32 acc. CTA 128x128xBK32, warp tile 64x64,
 * 4-stage cp.async, 2 CTAs/SM. All compact-M (guarded by cnt[z]).
 * NN=0: C=A*B^T (K-major); NN=1: C=A*B (B N-major, ldbn row stride).
 * MODE 1: scores: M,N guarded; fp32 out (ld 1024), *SCALE.
 * MODE 2: fused qkv: N spans 3 HID segments -> q/k/v, relu on segs 0,1.
 * MODE 3: compact generic: bias/relu opt, resh compact fp16 residual opt,
 *         Ch compact fp16 out opt, Cf = DENSE fp32 out scattered via gidx opt.
 *         If NN==1, K = pad32(cnt[z]) (PV case).
 * ------------------------------------------------------------------------ */
template<int NN, int MODE>
__global__ __launch_bounds__(NTHREADS, 2) void gemm_fp16(
    const fp16* __restrict__ A, const fp16* __restrict__ B,
    int K, int lda, int ldbn,
    size_t sA, size_t sB, size_t sC,
    float* __restrict__ Cf, fp16* __restrict__ Ch,
    fp16* __restrict__ Ch2, fp16* __restrict__ Ch3,
    int ldc,
    const float* __restrict__ bias, const float* __restrict__ bias2,
    const float* __restrict__ bias3,
    const fp16* __restrict__ resh,
    const int* __restrict__ cnt, const int* __restrict__ gidx, int relu)
{
    extern __shared__ char smraw[];
    const uint32_t sb = smem_u32(smraw);
    const int tid = threadIdx.x, lane = tid & 31, wid = tid >> 5;
    const int wm = wid & 1, wn = wid >> 1;
    const int z = blockIdx.z, bm = blockIdx.y * BM, bn = blockIdx.x * BN;

    const int nb = __ldg(cnt + z);
    if (bm >= nb) return;
    if (MODE == 1 && bn >= nb) return;
    if (MODE == 3 && NN == 1) K = (nb + 31) & ~31;

    const fp16* Ag = A + z * sA + (size_t)bm * lda;
    const fp16* Bg;
    if (NN) Bg = B + z * sB + bn;
    else    Bg = B + z * sB + (size_t)bn * K;

    float acc[4][8][4];
    #pragma unroll
    for (int i = 0; i < 4; i++)
        #pragma unroll
        for (int j = 0; j < 8; j++)
            #pragma unroll
            for (int t = 0; t < 4; t++) acc[i][j][t] = 0.f;

    auto issue = [&](int s) {
        const uint32_t stb = sb + (uint32_t)(s % NSTAGES) * STAGE_BYTES;
        const int k0 = s * BK;
        #pragma unroll
        for (int i = 0; i < 4; i++) {
            const int idx = tid + (i << 7);
            const int row = idx >> 2, c8 = (idx & 3) << 3;
            CP16(stb + row * 80 + (c8 << 1), Ag + (size_t)row * lda + k0 + c8);
        }
        if (!NN) {
            #pragma unroll
            for (int i = 0; i < 4; i++) {
                const int idx = tid + (i << 7);
                const int row = idx >> 2, c8 = (idx & 3) << 3;
                CP16(stb + STG + row * 80 + (c8 << 1), Bg + (size_t)row * K + k0 + c8);
            }
        } else {
            #pragma unroll
            for (int i = 0; i < 4; i++) {
                const int idx = tid + (i << 7);
                const int row = idx >> 4, c8 = (idx & 15) << 3;
                CP16(stb + STG + row * 272 + (c8 << 1), Bg + (size_t)(k0 + row) * ldbn + c8);
            }
        }
    };

    auto compute = [&](int s) {
        const uint32_t stb = sb + (uint32_t)(s % NSTAGES) * STAGE_BYTES;
        #pragma unroll
        for (int ks = 0; ks < 2; ks++) {
            uint32_t ah[4][4];
            #pragma unroll
            for (int i = 0; i < 4; i++) {
                const int arow = wm * 64 + i * 16 + (lane & 15);
                LDSM4(ah[i], stb + arow * 80 + ((ks * 16 + ((lane >> 4) << 3)) << 1));
            }
            #pragma unroll
            for (int p = 0; p < 4; p++) {
                uint32_t bh[4];
                if (!NN) {
                    const int brow = wn * 64 + p * 16 + (lane & 7) + ((lane >> 4) << 3);
                    LDSM4(bh, stb + STG + brow * 80 +
                              ((ks * 16 + (((lane >> 3) & 1) << 3)) << 1));
                } else {
                    const int krow = ks * 16 + (lane & 7) + (((lane >> 3) & 1) << 3);
                    const int ncol = wn * 64 + p * 16 + ((lane >> 4) << 3);
                    LDSM4T(bh, stb + STG + krow * 272 + (ncol << 1));
                }
                #pragma unroll
                for (int i = 0; i < 4; i++)
                    #pragma unroll
                    for (int jj = 0; jj < 2; jj++)
                        MMA(acc[i][p * 2 + jj], ah[i], bh[jj * 2], bh[jj * 2 + 1]);
            }
        }
    };

    const int NSt = K / BK;
    issue(0); CPCOMMIT();
    if (NSt > 1) issue(1); CPCOMMIT();
    if (NSt > 2) issue(2); CPCOMMIT();
    for (int s = 0; s < NSt; s++) {
        CPWAIT2();
        __syncthreads();
        if (s + 3 < NSt) issue(s + 3);
        CPCOMMIT();
        compute(s);
    }

    /* ---- epilogue ---- */
    if (MODE == 1) {                       /* compact scores, fp32 */
        float* Cfz = Cf + (size_t)z * sC;
        #pragma unroll
        for (int i = 0; i < 4; i++) {
            const int j0 = bm + wm * 64 + i * 16 + (lane >> 2);
            const int j1 = j0 + 8;
            #pragma unroll
            for (int j = 0; j < 8; j++) {
                const int c = bn + wn * 64 + j * 8 + ((lane & 3) << 1);
                if (j0 < nb)
                    *(float2*)&Cfz[(size_t)j0 * ldc + c] =
                        make_float2(acc[i][j][0] * SCALE_QK, acc[i][j][1] * SCALE_QK);
                if (j1 < nb)
                    *(float2*)&Cfz[(size_t)j1 * ldc + c] =
                        make_float2(acc[i][j][2] * SCALE_QK, acc[i][j][3] * SCALE_QK);
            }
        }
    } else if (MODE == 2) {                /* compact qkv routing */
        const int seg = bn / HID;
        fp16* dst = (seg == 0) ? Ch : (seg == 1) ? Ch2 : Ch3;
        const float* bs = (seg == 0) ? bias : (seg == 1) ? bias2 : bias3;
        const int cb = bn - seg * HID;
        const int dorelu = (seg < 2);
        #pragma unroll
        for (int i = 0; i < 4; i++) {
            const int j0 = bm + wm * 64 + i * 16 + (lane >> 2);
            const int j1 = j0 + 8;
            #pragma unroll
            for (int j = 0; j < 8; j++) {
                const int cl = cb + wn * 64 + j * 8 + ((lane & 3) << 1);
                const float b0v = bs[cl], b1v = bs[cl + 1];
                float ax = acc[i][j][0] + b0v, ay = acc[i][j][1] + b1v;
                float az = acc[i][j][2] + b0v, aw = acc[i][j][3] + b1v;
                if (dorelu) {
                    ax = fmaxf(ax, 0.f); ay = fmaxf(ay, 0.f);
                    az = fmaxf(az, 0.f); aw = fmaxf(aw, 0.f);
                }
                if (j0 < nb)
                    *(uint32_t*)((char*)dst + (((size_t)z * SEQ + j0) * HID + cl) * 2) =
                        pack_h2(ax, ay);
                if (j1 < nb)
                    *(uint32_t*)((char*)dst + (((size_t)z * SEQ + j1) * HID + cl) * 2) =
                        pack_h2(az, aw);
            }
        }
    } else {                               /* MODE 3: compact generic */
        const fp16* rz = resh ? (resh + z * sC) : (const fp16*)0;
        fp16* Chz = Ch ? (Ch + z * sC) : (fp16*)0;
        #pragma unroll
        for (int i = 0; i < 4; i++) {
            const int j0 = bm + wm * 64 + i * 16 + (lane >> 2);
            const int j1 = j0 + 8;
            const int ok0 = (j0 < nb), ok1 = (j1 < nb);
            const int s0 = (Cf && ok0) ? __ldg(gidx + z * SEQ + j0) : 0;
            const int s1 = (Cf && ok1) ? __ldg(gidx + z * SEQ + j1) : 0;
            #pragma unroll
            for (int j = 0; j < 8; j++) {
                const int c = bn + wn * 64 + j * 8 + ((lane & 3) << 1);
                float ax = acc[i][j][0], ay = acc[i][j][1];
                float az = acc[i][j][2], aw = acc[i][j][3];
                if (bias) {
                    const float b0v = bias[c], b1v = bias[c + 1];
                    ax += b0v; ay += b1v; az += b0v; aw += b1v;
                }
                if (relu) {
                    ax = fmaxf(ax, 0.f); ay = fmaxf(ay, 0.f);
                    az = fmaxf(az, 0.f); aw = fmaxf(aw, 0.f);
                }
                if (rz) {
                    if (ok0) {
                        const __half2 q0 = *(const __half2*)((const char*)rz +
                            ((size_t)j0 * ldc + c) * 2);
                        const float2 f0 = __half22float2(q0);
                        ax += f0.x; ay += f0.y;
                    }
                    if (ok1) {
                        const __half2 q1 = *(const __half2*)((const char*)rz +
                            ((size_t)j1 * ldc + c) * 2);
                        const float2 f1 = __half22float2(q1);
                        az += f1.x; aw += f1.y;
                    }
                }
                if (Chz) {
                    if (ok0)
                        *(uint32_t*)((char*)Chz + ((size_t)j0 * ldc + c) * 2) = pack_h2(ax, ay);
                    if (ok1)
                        *(uint32_t*)((char*)Chz + ((size_t)j1 * ldc + c) * 2) = pack_h2(az, aw);
                }
                if (Cf) {
                    if (ok0)
                        *(float2*)&Cf[((size_t)z * SEQ + s0) * HID + c] = make_float2(ax, ay);
                    if (ok1)
                        *(float2*)&Cf[((size_t)z * SEQ + s1) * HID + c] = make_float2(az, aw);
                }
            }
        }
    }
}

/* ---- compact softmax: warp-per-row, 3-pass log-sum-exp, fp16 out ---- */
__global__ __launch_bounds__(256) void softmax_c_kernel(
    const float* __restrict__ Sc, fp16* __restrict__ Wout,
    const int* __restrict__ cnt)
{
    const int b = blockIdx.y;
    const int nb = __ldg(cnt + b);
    const int row = (blockIdx.x << 3) + (threadIdx.x >> 5);   /* 8 warps/block */
    if (row >= nb) return;
    const int lane = threadIdx.x & 31;
    const float* srow = Sc + ((size_t)b * SEQ + row) * SEQ;

    float mx = -3.0e38f;
    for (int t = lane; t < nb; t += 32) mx = fmaxf(mx, srow[t]);
    #pragma unroll
    for (int o = 16; o > 0; o >>= 1) mx = fmaxf(mx, __shfl_xor_sync(~0u, mx, o));

    float s = 0.f;
    for (int t = lane; t < nb; t += 32) s += expf(srow[t] - mx);
    #pragma unroll
    for (int o = 16; o > 0; o >>= 1) s += __shfl_xor_sync(~0u, s, o);

    const float lse = mx + logf(s);
    const int pad = (nb + 31) & ~31;
    fp16* wrow = Wout + ((size_t)b * SEQ + row) * SEQ;
    for (int t = lane; t < pad; t += 32) {
        const float v = (t < nb) ? expf(srow[t] - lse) : 0.f;
        wrow[t] = __float2half_rn(v);
    }
}

/* --------------------------------------------------------------------- */
extern "C" void kernel_launch(void* const* d_in, const int* in_sizes, int n_in,
                              void* d_out, int out_size)
{
    const float* x    = (const float*)d_in[0];
    const int*   mask = (const int*)  d_in[1];
    const float* Wq = (const float*)d_in[2];
    const float* bq = (const float*)d_in[3];
    const float* Wk = (const float*)d_in[4];
    const float* bk = (const float*)d_in[5];
    const float* Wv = (const float*)d_in[6];
    const float* bv = (const float*)d_in[7];
    const float* W1 = (const float*)d_in[8];
    const float* b1 = (const float*)d_in[9];
    const float* W2 = (const float*)d_in[10];
    const float* b2 = (const float*)d_in[11];
    float* out = (float*)d_out;

    fp16 *xc,*qh,*kh,*vh,*oc,*h1h,*wqkv,*w1h,*w2h,*wh;
    float *sc, *cvec; int *gidx, *cnt;
    cudaGetSymbolAddress((void**)&xc,   g_xc);
    cudaGetSymbolAddress((void**)&qh,   g_q);
    cudaGetSymbolAddress((void**)&kh,   g_k);
    cudaGetSymbolAddress((void**)&vh,   g_v);
    cudaGetSymbolAddress((void**)&oc,   g_oc);
    cudaGetSymbolAddress((void**)&h1h,  g_h1);
    cudaGetSymbolAddress((void**)&wqkv, g_wqkv);
    cudaGetSymbolAddress((void**)&w1h,  g_w1);
    cudaGetSymbolAddress((void**)&w2h,  g_w2);
    cudaGetSymbolAddress((void**)&wh,   g_w);
    cudaGetSymbolAddress((void**)&sc,   g_sc);
    cudaGetSymbolAddress((void**)&gidx, g_idx);
    cudaGetSymbolAddress((void**)&cnt,  g_cnt);
    cudaGetSymbolAddress((void**)&cvec, g_cvec);

    cudaFuncSetAttribute(gemm_fp16<0,1>, cudaFuncAttributeMaxDynamicSharedMemorySize, SMEM_GEMM);
    cudaFuncSetAttribute(gemm_fp16<0,2>, cudaFuncAttributeMaxDynamicSharedMemorySize, SMEM_GEMM);
    cudaFuncSetAttribute(gemm_fp16<1,3>, cudaFuncAttributeMaxDynamicSharedMemorySize, SMEM_GEMM);
    cudaFuncSetAttribute(gemm_fp16<0,3>, cudaFuncAttributeMaxDynamicSharedMemorySize, SMEM_GEMM);

    dim3 blk(NTHREADS);
    const size_t sBH = (size_t)SEQ * HID, sBS = (size_t)SEQ * SEQ;
    dim3 gqkv(3 * HID / BN, SEQ / BM, NB);        /* (18, 8, 16) compact-M */
    dim3 gsc(SEQ / BN, SEQ / BM, NB);             /* (8, 8, 16) compact-MN */
    dim3 gpv(HID / BN, SEQ / BM, NB);             /* (6, 8, 16) compact-M, var-K */
    dim3 gffn(HID / BN, SEQ / BM, NB);            /* (6, 8, 16) compact-M */

    idx_kernel<<<NB, 32>>>(mask, gidx, cnt);                                       /* 0 */
    cvt_w5_kernel<<<dim3((NWE/2 + 255)/256, 5), 256>>>(Wq, Wk, Wv, W1, W2,
        (uint32_t*)wqkv, (uint32_t*)w1h, (uint32_t*)w2h, NWE/2);                   /* 1 */
    gather_x_kernel<<<dim3(SEQ, NB), 192>>>(x, gidx, cnt, (uint32_t*)xc);          /* 2 */
    cvec_kernel<<<HID, 256>>>(b1, W2, b2, cvec);                                   /* 3 */

    /* fused compact q,k,v projection */
    gemm_fp16<0,2><<<gqkv, blk, SMEM_GEMM>>>(xc, wqkv, HID, HID, 0, sBH, 0, 0,
        nullptr, qh, kh, vh, HID, bq, bk, bv, nullptr, cnt, gidx, 0);              /* 4 */

    /* compact scores (launch index 5 — profiled) */
    gemm_fp16<0,1><<<gsc, blk, SMEM_GEMM>>>(qh, kh, HID, HID, 0, sBH, sBH, sBS,
        sc, nullptr, nullptr, nullptr, SEQ, nullptr, nullptr, nullptr,
        nullptr, cnt, gidx, 0);                                                    /* 5 */

    softmax_c_kernel<<<dim3(SEQ / 8, NB), 256>>>(sc, wh, cnt);                     /* 6 */

    /* compact PV -> compact o */
    gemm_fp16<1,3><<<gpv, blk, SMEM_GEMM>>>(wh, vh, SEQ, SEQ, HID, sBS, sBH, sBH,
        nullptr, oc, nullptr, nullptr, HID, nullptr, nullptr, nullptr,
        nullptr, cnt, gidx, 0);                                                    /* 7 */

    fill_masked_kernel<<<dim3(SEQ, NB), 192>>>(mask, cvec, out);                   /* 8 */

    /* compact FFN */
    gemm_fp16<0,3><<<gffn, blk, SMEM_GEMM>>>(oc, w1h, HID, HID, 0, sBH, 0, sBH,
        nullptr, h1h, nullptr, nullptr, HID, b1, nullptr, nullptr,
        nullptr, cnt, gidx, 1);                                                    /* 9 */
    gemm_fp16<0,3><<<gffn, blk, SMEM_GEMM>>>(h1h, w2h, HID, HID, 0, sBH, 0, sBH,
        out, nullptr, nullptr, nullptr, HID, b2, nullptr, nullptr,
        oc, cnt, gidx, 0);                                                         /* 10 */
}